// round 16
// baseline (speedup 1.0000x reference)
#include <cuda_runtime.h>
#include <cuda_bf16.h>
#include <math.h>
#include <stdint.h>

#define BB 2
#define SS 4096
#define DD 128
#define HALF 64
#define TQ 32
#define KROWS (TQ + 2*HALF)   /* 160 */
#define NEG_INF_F (-1e30f)

#define S136 136               /* bf16 elems per row (272 B stride) */

// Split bf16 q/k/v produced by qkv kernel (hi + lo Dekker halves).
__device__ __nv_bfloat16 g_qh[BB*SS*DD], g_ql[BB*SS*DD];
__device__ __nv_bfloat16 g_kh[BB*SS*DD], g_kl[BB*SS*DD];
__device__ __nv_bfloat16 g_vh[BB*SS*DD], g_vl[BB*SS*DD];

// Pre-converted ROW-MAJOR W (no transpose): W[k][n] as bf16 hi/lo, stride S136.
__device__ __nv_bfloat16 g_w_hi[3][128*S136];
__device__ __nv_bfloat16 g_w_lo[3][128*S136];

__device__ __forceinline__ void mma16816(float* d, const uint32_t* a,
                                         const uint32_t* b) {
    asm volatile(
        "mma.sync.aligned.m16n8k16.row.col.f32.bf16.bf16.f32 "
        "{%0,%1,%2,%3}, {%4,%5,%6,%7}, {%8,%9}, {%0,%1,%2,%3};\n"
        : "+f"(d[0]), "+f"(d[1]), "+f"(d[2]), "+f"(d[3])
        : "r"(a[0]), "r"(a[1]), "r"(a[2]), "r"(a[3]), "r"(b[0]), "r"(b[1]));
}

__device__ __forceinline__ void ldmx2t(uint32_t& b0, uint32_t& b1, uint32_t a) {
    asm volatile("ldmatrix.sync.aligned.m8n8.x2.trans.shared.b16 {%0,%1}, [%2];"
                 : "=r"(b0), "=r"(b1) : "r"(a));
}

__device__ __forceinline__ uint32_t smem_u32(const void* p) {
    uint32_t a;
    asm("{ .reg .u64 t; cvta.to.shared.u64 t, %1; cvt.u32.u64 %0, t; }"
        : "=r"(a) : "l"(p));
    return a;
}

__device__ __forceinline__ __nv_bfloat162 split_hi2(float x, float y) {
    return __nv_bfloat162(__float2bfloat16(x), __float2bfloat16(y));
}
__device__ __forceinline__ __nv_bfloat162 split_lo2(float x, float y) {
    float hx = __bfloat162float(__float2bfloat16(x));
    float hy = __bfloat162float(__float2bfloat16(y));
    return __nv_bfloat162(__float2bfloat16(x - hx), __float2bfloat16(y - hy));
}

// ====== one-shot W convert: pure elementwise, STG.64-packed ======

__global__ void __launch_bounds__(256) wconv_kernel(
    const float* __restrict__ Wq, const float* __restrict__ Wk,
    const float* __restrict__ Wv)
{
    const float* Wm[3] = {Wq, Wk, Wv};
    const float* Wg = Wm[blockIdx.x];
    __nv_bfloat16* whi = g_w_hi[blockIdx.x];
    __nv_bfloat16* wlo = g_w_lo[blockIdx.x];
    const int tid = threadIdx.x;
    const int k = blockIdx.y * 8 + (tid >> 5);
    const int n = (tid & 31) << 2;

    float4 w = *(const float4*)(Wg + (size_t)k * DD + n);
    int o = k * S136 + n;
    __nv_bfloat162 h01 = split_hi2(w.x, w.y), h23 = split_hi2(w.z, w.w);
    __nv_bfloat162 l01 = split_lo2(w.x, w.y), l23 = split_lo2(w.z, w.w);
    *(uint2*)(whi + o) = make_uint2(*(uint32_t*)&h01, *(uint32_t*)&h23);
    *(uint2*)(wlo + o) = make_uint2(*(uint32_t*)&l01, *(uint32_t*)&l23);
}

// ===================== QKV: double-buffered W, copy/MMA overlap ============
// smem: x_hi@0 x_lo@17408 | Wbuf0@34816 (hi+lo 69632) | Wbuf1@104448

#define OFF_XHI 0
#define OFF_XLO 17408
#define OFF_W0  34816
#define OFF_W1  104448
#define WHALF   34816          /* hi->lo offset inside a W buffer */
#define W_U4    2176           /* uint4 count per hi (or lo) array */
#define W_U4_KS 272            /* per-kstep copy slice (2176/8) */
#define QKV_SMEM 174080

__global__ void __launch_bounds__(256) qkv_mma_kernel(
    const float* __restrict__ x,
    const float* __restrict__ bq, const float* __restrict__ bk,
    const float* __restrict__ bv)
{
    extern __shared__ char sb[];
    const uint32_t sbase = smem_u32(sb);
    const int tid  = threadIdx.x;
    const int wid  = tid >> 5;
    const int lane = tid & 31;
    const int row0 = blockIdx.x * 64;

    // ---- convert x tile + preload W0 into buf0 ----
    for (int idx = tid; idx < 64 * 32; idx += 256) {
        int r = idx >> 5, k = (idx & 31) << 2;
        float4 v = *(const float4*)(x + (size_t)(row0 + r) * DD + k);
        int off = (r * S136 + k) * 2;
        *(__nv_bfloat162*)(sb + OFF_XHI + off)     = split_hi2(v.x, v.y);
        *(__nv_bfloat162*)(sb + OFF_XHI + off + 4) = split_hi2(v.z, v.w);
        *(__nv_bfloat162*)(sb + OFF_XLO + off)     = split_lo2(v.x, v.y);
        *(__nv_bfloat162*)(sb + OFF_XLO + off + 4) = split_lo2(v.z, v.w);
    }
    {
        const uint4* shi = (const uint4*)g_w_hi[0];
        const uint4* slo = (const uint4*)g_w_lo[0];
        uint4* dhi = (uint4*)(sb + OFF_W0);
        uint4* dlo = (uint4*)(sb + OFF_W0 + WHALF);
        for (int i = tid; i < W_U4; i += 256) {
            dhi[i] = shi[i];
            dlo[i] = slo[i];
        }
    }
    __syncthreads();

    const float* bias[3] = {bq, bk, bv};
    __nv_bfloat16* outh[3];
    __nv_bfloat16* outl[3];
    outh[0] = g_qh; outh[1] = g_kh; outh[2] = g_vh;
    outl[0] = g_ql; outl[1] = g_kl; outl[2] = g_vl;

    const int mw = wid & 1;
    const int nw = wid >> 1;
    const int ar = lane >> 2;
    const int ac = (lane & 3) << 2;

    for (int m = 0; m < 3; ++m) {
        const uint32_t wcur = (m & 1) ? OFF_W1 : OFF_W0;
        const uint32_t wnxt = (m & 1) ? OFF_W0 : OFF_W1;
        const uint4* nhi = (m < 2) ? (const uint4*)g_w_hi[m + 1] : (const uint4*)0;
        const uint4* nlo = (m < 2) ? (const uint4*)g_w_lo[m + 1] : (const uint4*)0;
        uint4* dnh = (uint4*)(sb + wnxt);
        uint4* dnl = (uint4*)(sb + wnxt + WHALF);

        float acc[2][4][4];
        #pragma unroll
        for (int mt = 0; mt < 2; ++mt)
            #pragma unroll
            for (int nt = 0; nt < 4; ++nt)
                #pragma unroll
                for (int e = 0; e < 4; ++e) acc[mt][nt][e] = 0.f;

        #pragma unroll
        for (int ks = 0; ks < 8; ++ks) {
            // strip-mined copy of next W (hidden behind MMA)
            if (m < 2) {
                for (int i = tid + ks * W_U4_KS; i < (ks + 1) * W_U4_KS; i += 256) {
                    dnh[i] = nhi[i];
                    dnl[i] = nlo[i];
                }
            }
            const int kb = ks * 32;
            uint32_t ahi[2][4], alo[2][4];
            #pragma unroll
            for (int mt = 0; mt < 2; ++mt) {
                int abase = (mw * 32 + mt * 16 + ar) * 272 + kb + ac;
                ahi[mt][0] = *(const uint32_t*)(sb + OFF_XHI + abase);
                ahi[mt][1] = *(const uint32_t*)(sb + OFF_XHI + abase + 8*272);
                ahi[mt][2] = *(const uint32_t*)(sb + OFF_XHI + abase + 16);
                ahi[mt][3] = *(const uint32_t*)(sb + OFF_XHI + abase + 8*272 + 16);
                alo[mt][0] = *(const uint32_t*)(sb + OFF_XLO + abase);
                alo[mt][1] = *(const uint32_t*)(sb + OFF_XLO + abase + 8*272);
                alo[mt][2] = *(const uint32_t*)(sb + OFF_XLO + abase + 16);
                alo[mt][3] = *(const uint32_t*)(sb + OFF_XLO + abase + 8*272 + 16);
            }
            const uint32_t wrow = sbase + wcur + (ks * 16 + (lane & 15)) * 272;
            #pragma unroll
            for (int nt = 0; nt < 4; ++nt) {
                int n0 = nw * 32 + nt * 8;
                uint32_t bhi[2], blo[2];
                ldmx2t(bhi[0], bhi[1], wrow + n0 * 2);
                ldmx2t(blo[0], blo[1], wrow + WHALF + n0 * 2);
                #pragma unroll
                for (int mt = 0; mt < 2; ++mt) {
                    mma16816(acc[mt][nt], ahi[mt], bhi);
                    mma16816(acc[mt][nt], ahi[mt], blo);
                    mma16816(acc[mt][nt], alo[mt], bhi);
                }
            }
        }

        // ---- epilogue: acc + bias -> split hi/lo bf16 globals ----
        const float* bp = bias[m];
        __nv_bfloat16* oh = outh[m];
        __nv_bfloat16* ol = outl[m];
        #pragma unroll
        for (int mt = 0; mt < 2; ++mt) {
            int grow = row0 + mw * 32 + mt * 16 + ar;
            #pragma unroll
            for (int nt = 0; nt < 4; ++nt) {
                int c = nw * 32 + nt * 8 + ((lane & 3) << 1);
                float2 b2 = *(const float2*)(bp + c);
                float v0x = acc[mt][nt][0] + b2.x;
                float v0y = acc[mt][nt][1] + b2.y;
                float v1x = acc[mt][nt][2] + b2.x;
                float v1y = acc[mt][nt][3] + b2.y;
                size_t o0 = (size_t)grow * DD + c;
                size_t o1 = (size_t)(grow + 8) * DD + c;
                *(__nv_bfloat162*)(oh + o0) = split_hi2(v0x, v0y);
                *(__nv_bfloat162*)(ol + o0) = split_lo2(v0x, v0y);
                *(__nv_bfloat162*)(oh + o1) = split_hi2(v1x, v1y);
                *(__nv_bfloat162*)(ol + o1) = split_lo2(v1x, v1y);
            }
        }
        if (m < 2) __syncthreads();   // next-W copy complete; cur reads done
    }
}

// ===== attention: fragment-native softmax, single-phase PV (R14) =====

#define AT_KHI 0
#define AT_KLO 43520
#define AT_QHI 87040
#define AT_QLO 95744
#define AT_VH   0
#define AT_VL   43520
#define AT_PTH  87040
#define AT_PTL  97792
#define AT_PMAX 108544
#define AT_PSUM 109056
#define AT_WS   109568
#define PTST 336
#define ATTN_SMEM 109696

__global__ void __launch_bounds__(256, 2) attn_kernel(float* __restrict__ outp)
{
    extern __shared__ char sb[];
    const uint32_t sbase = smem_u32(sb);
    const int tid  = threadIdx.x;
    const int wid  = tid >> 5;
    const int lane = tid & 31;
    const int blk  = blockIdx.x;
    const int b    = blk >> 7;
    const int s0   = (blk & 127) * TQ;
    const int lo   = s0 - HALF;

    const __nv_bfloat16* kh = g_kh + (size_t)b * SS * DD;
    const __nv_bfloat16* kl = g_kl + (size_t)b * SS * DD;
    const __nv_bfloat16* vh = g_vh + (size_t)b * SS * DD;
    const __nv_bfloat16* vl = g_vl + (size_t)b * SS * DD;
    const __nv_bfloat16* qh = g_qh + (size_t)b * SS * DD;
    const __nv_bfloat16* ql = g_ql + (size_t)b * SS * DD;

    for (int idx = tid; idx < KROWS * 16; idx += 256) {
        int r = idx >> 4, c = idx & 15;
        int g = lo + r;
        uint4 h = make_uint4(0,0,0,0), l = make_uint4(0,0,0,0);
        if ((unsigned)g < SS) {
            h = *(const uint4*)(kh + (size_t)g * DD + (c << 3));
            l = *(const uint4*)(kl + (size_t)g * DD + (c << 3));
        }
        *(uint4*)(sb + AT_KHI + r * 272 + (c << 4)) = h;
        *(uint4*)(sb + AT_KLO + r * 272 + (c << 4)) = l;
    }
    for (int idx = tid; idx < TQ * 16; idx += 256) {
        int r = idx >> 4, c = idx & 15;
        *(uint4*)(sb + AT_QHI + r * 272 + (c << 4)) =
            *(const uint4*)(qh + (size_t)(s0 + r) * DD + (c << 3));
        *(uint4*)(sb + AT_QLO + r * 272 + (c << 4)) =
            *(const uint4*)(ql + (size_t)(s0 + r) * DD + (c << 3));
    }
    __syncthreads();

    const int mt = wid & 1;
    const int ng = wid >> 1;
    const int ar = lane >> 2;
    const int ac = (lane & 3) << 2;

    float sacc[5][4];
    #pragma unroll
    for (int nt = 0; nt < 5; ++nt)
        #pragma unroll
        for (int e = 0; e < 4; ++e) sacc[nt][e] = 0.f;

    #pragma unroll
    for (int ks = 0; ks < 8; ++ks) {
        const int kb = ks * 32;
        const int abase = (mt * 16 + ar) * 272 + kb + ac;
        uint32_t ahi[4], alo[4];
        ahi[0] = *(const uint32_t*)(sb + AT_QHI + abase);
        ahi[1] = *(const uint32_t*)(sb + AT_QHI + abase + 8*272);
        ahi[2] = *(const uint32_t*)(sb + AT_QHI + abase + 16);
        ahi[3] = *(const uint32_t*)(sb + AT_QHI + abase + 8*272 + 16);
        alo[0] = *(const uint32_t*)(sb + AT_QLO + abase);
        alo[1] = *(const uint32_t*)(sb + AT_QLO + abase + 8*272);
        alo[2] = *(const uint32_t*)(sb + AT_QLO + abase + 16);
        alo[3] = *(const uint32_t*)(sb + AT_QLO + abase + 8*272 + 16);
        #pragma unroll
        for (int nt = 0; nt < 5; ++nt) {
            int bbase = (ng * 40 + nt * 8 + ar) * 272 + kb + ac;
            uint32_t bhi[2], blo[2];
            bhi[0] = *(const uint32_t*)(sb + AT_KHI + bbase);
            bhi[1] = *(const uint32_t*)(sb + AT_KHI + bbase + 16);
            blo[0] = *(const uint32_t*)(sb + AT_KLO + bbase);
            blo[1] = *(const uint32_t*)(sb + AT_KLO + bbase + 16);
            mma16816(sacc[nt], ahi, bhi);
            mma16816(sacc[nt], ahi, blo);
            mma16816(sacc[nt], alo, bhi);
        }
    }

    const float scale = 0.08838834764831844f;
    const int r0 = mt * 16 + ar;
    const int r1 = r0 + 8;
    float gm0 = -INFINITY, gm1 = -INFINITY;
    #pragma unroll
    for (int nt = 0; nt < 5; ++nt) {
        int colb = ng * 40 + nt * 8 + ((lane & 3) << 1);
        #pragma unroll
        for (int u = 0; u < 2; ++u) {
            int col = colb + u;
            int g = lo + col;
            bool okg = ((unsigned)g < SS);
            int j0 = col - r0, j1 = col - r1;
            float v0 = (okg && j0 >= 0 && j0 <= 128) ? sacc[nt][u]   * scale : NEG_INF_F;
            float v1 = (okg && j1 >= 0 && j1 <= 128) ? sacc[nt][2+u] * scale : NEG_INF_F;
            sacc[nt][u]   = v0;
            sacc[nt][2+u] = v1;
            gm0 = fmaxf(gm0, v0);
            gm1 = fmaxf(gm1, v1);
        }
    }
    gm0 = fmaxf(gm0, __shfl_xor_sync(0xffffffffu, gm0, 1));
    gm0 = fmaxf(gm0, __shfl_xor_sync(0xffffffffu, gm0, 2));
    gm1 = fmaxf(gm1, __shfl_xor_sync(0xffffffffu, gm1, 1));
    gm1 = fmaxf(gm1, __shfl_xor_sync(0xffffffffu, gm1, 2));
    float ps0 = 0.f, ps1 = 0.f;
    #pragma unroll
    for (int nt = 0; nt < 5; ++nt) {
        #pragma unroll
        for (int u = 0; u < 2; ++u) {
            float e0 = __expf(sacc[nt][u]   - gm0);
            float e1 = __expf(sacc[nt][2+u] - gm1);
            sacc[nt][u]   = e0;
            sacc[nt][2+u] = e1;
            ps0 += e0;
            ps1 += e1;
        }
    }
    ps0 += __shfl_xor_sync(0xffffffffu, ps0, 1);
    ps0 += __shfl_xor_sync(0xffffffffu, ps0, 2);
    ps1 += __shfl_xor_sync(0xffffffffu, ps1, 1);
    ps1 += __shfl_xor_sync(0xffffffffu, ps1, 2);
    if ((lane & 3) == 0) {
        ((float*)(sb + AT_PMAX))[r0 * 4 + ng] = gm0;
        ((float*)(sb + AT_PMAX))[r1 * 4 + ng] = gm1;
        ((float*)(sb + AT_PSUM))[r0 * 4 + ng] = ps0;
        ((float*)(sb + AT_PSUM))[r1 * 4 + ng] = ps1;
    }
    __syncthreads();

    for (int idx = tid; idx < KROWS * 16; idx += 256) {
        int r = idx >> 4, c = idx & 15;
        int gc = min(max(lo + r, 0), SS - 1);
        *(uint4*)(sb + AT_VH + r * 272 + (c << 4)) =
            *(const uint4*)(vh + (size_t)gc * DD + (c << 3));
        *(uint4*)(sb + AT_VL + r * 272 + (c << 4)) =
            *(const uint4*)(vl + (size_t)gc * DD + (c << 3));
    }

    {
        float4 m40 = *(const float4*)((const float*)(sb + AT_PMAX) + r0 * 4);
        float4 m41 = *(const float4*)((const float*)(sb + AT_PMAX) + r1 * 4);
        float4 s40 = *(const float4*)((const float*)(sb + AT_PSUM) + r0 * 4);
        float4 s41 = *(const float4*)((const float*)(sb + AT_PSUM) + r1 * 4);
        float m0 = fmaxf(fmaxf(m40.x, m40.y), fmaxf(m40.z, m40.w));
        float m1 = fmaxf(fmaxf(m41.x, m41.y), fmaxf(m41.z, m41.w));
        float s0w = s40.x * __expf(m40.x - m0) + s40.y * __expf(m40.y - m0)
                  + s40.z * __expf(m40.z - m0) + s40.w * __expf(m40.w - m0);
        float s1w = s41.x * __expf(m41.x - m1) + s41.y * __expf(m41.y - m1)
                  + s41.z * __expf(m41.z - m1) + s41.w * __expf(m41.w - m1);
        if ((lane & 3) == 0 && ng == 0) {
            ((float*)(sb + AT_WS))[r0] = s0w;
            ((float*)(sb + AT_WS))[r1] = s1w;
        }
        float f0 = __expf(gm0 - m0);
        float f1 = __expf(gm1 - m1);
        #pragma unroll
        for (int nt = 0; nt < 5; ++nt) {
            int cb = (ng * 40 + nt * 8 + ((lane & 3) << 1)) * 2;
            float p00 = sacc[nt][0] * f0, p01 = sacc[nt][1] * f0;
            float p10 = sacc[nt][2] * f1, p11 = sacc[nt][3] * f1;
            *(__nv_bfloat162*)(sb + AT_PTH + r0 * PTST + cb) = split_hi2(p00, p01);
            *(__nv_bfloat162*)(sb + AT_PTL + r0 * PTST + cb) = split_lo2(p00, p01);
            *(__nv_bfloat162*)(sb + AT_PTH + r1 * PTST + cb) = split_hi2(p10, p11);
            *(__nv_bfloat162*)(sb + AT_PTL + r1 * PTST + cb) = split_lo2(p10, p11);
        }
    }
    __syncthreads();

    float oacc[4][4];
    #pragma unroll
    for (int nt = 0; nt < 4; ++nt)
        #pragma unroll
        for (int e = 0; e < 4; ++e) oacc[nt][e] = 0.f;

    #pragma unroll
    for (int ks = 0; ks < 10; ++ks) {
        const int abase = (mt * 16 + ar) * PTST + ks * 32 + ac;
        uint32_t phi[4], plo[4];
        phi[0] = *(const uint32_t*)(sb + AT_PTH + abase);
        phi[1] = *(const uint32_t*)(sb + AT_PTH + abase + 8*PTST);
        phi[2] = *(const uint32_t*)(sb + AT_PTH + abase + 16);
        phi[3] = *(const uint32_t*)(sb + AT_PTH + abase + 8*PTST + 16);
        plo[0] = *(const uint32_t*)(sb + AT_PTL + abase);
        plo[1] = *(const uint32_t*)(sb + AT_PTL + abase + 8*PTST);
        plo[2] = *(const uint32_t*)(sb + AT_PTL + abase + 16);
        plo[3] = *(const uint32_t*)(sb + AT_PTL + abase + 8*PTST + 16);
        const uint32_t vrow = sbase + AT_VH + (ks * 16 + (lane & 15)) * 272;
        #pragma unroll
        for (int nt = 0; nt < 4; ++nt) {
            int n0 = ng * 32 + nt * 8;
            uint32_t vhf[2], vlf[2];
            ldmx2t(vhf[0], vhf[1], vrow + n0 * 2);
            ldmx2t(vlf[0], vlf[1], vrow + (AT_VL - AT_VH) + n0 * 2);
            mma16816(oacc[nt], phi, vhf);
            mma16816(oacc[nt], phi, vlf);
            mma16816(oacc[nt], plo, vhf);
        }
    }

    {
        const float* ws = (const float*)(sb + AT_WS);
        float inv0 = 1.0f / ws[r0];
        float inv1 = 1.0f / ws[r1];
        float* op0 = outp + ((size_t)b * SS + s0 + r0) * DD;
        float* op1 = outp + ((size_t)b * SS + s0 + r1) * DD;
        #pragma unroll
        for (int nt = 0; nt < 4; ++nt) {
            int c = ng * 32 + nt * 8 + ((lane & 3) << 1);
            *(float2*)(op0 + c) = make_float2(oacc[nt][0] * inv0, oacc[nt][1] * inv0);
            *(float2*)(op1 + c) = make_float2(oacc[nt][2] * inv1, oacc[nt][3] * inv1);
        }
    }
}

extern "C" void kernel_launch(void* const* d_in, const int* in_sizes, int n_in,
                              void* d_out, int out_size)
{
    const float* x  = (const float*)d_in[0];
    const float* Wq = (const float*)d_in[1];
    const float* bq = (const float*)d_in[2];
    const float* Wk = (const float*)d_in[3];
    const float* bk = (const float*)d_in[4];
    const float* Wv = (const float*)d_in[5];
    const float* bv = (const float*)d_in[6];
    float* out = (float*)d_out;

    cudaFuncSetAttribute(qkv_mma_kernel,
                         cudaFuncAttributeMaxDynamicSharedMemorySize, QKV_SMEM);
    cudaFuncSetAttribute(attn_kernel,
                         cudaFuncAttributeMaxDynamicSharedMemorySize, ATTN_SMEM);

    wconv_kernel<<<dim3(3, 16), 256>>>(Wq, Wk, Wv);
    qkv_mma_kernel<<<BB * SS / 64, 256, QKV_SMEM>>>(x, bq, bk, bv);
    attn_kernel<<<BB * SS / TQ, 256, ATTN_SMEM>>>(out);
}

// round 17
// speedup vs baseline: 1.2553x; 1.2553x over previous
#include <cuda_runtime.h>
#include <cuda_bf16.h>
#include <math.h>
#include <stdint.h>

#define BB 2
#define SS 4096
#define DD 128
#define HALF 64
#define TQ 32
#define KROWS (TQ + 2*HALF)   /* 160 */
#define NEG_INF_F (-1e30f)

#define S136 136               /* bf16 elems per row (272 B stride) */

// Split bf16 q/k/v produced by qkv kernel (hi + lo Dekker halves).
__device__ __nv_bfloat16 g_qh[BB*SS*DD], g_ql[BB*SS*DD];
__device__ __nv_bfloat16 g_kh[BB*SS*DD], g_kl[BB*SS*DD];
__device__ __nv_bfloat16 g_vh[BB*SS*DD], g_vl[BB*SS*DD];

// Pre-converted ROW-MAJOR W (no transpose): W[k][n] as bf16 hi/lo, stride S136.
__device__ __nv_bfloat16 g_w_hi[3][128*S136];
__device__ __nv_bfloat16 g_w_lo[3][128*S136];

__device__ __forceinline__ void mma16816(float* d, const uint32_t* a,
                                         const uint32_t* b) {
    asm volatile(
        "mma.sync.aligned.m16n8k16.row.col.f32.bf16.bf16.f32 "
        "{%0,%1,%2,%3}, {%4,%5,%6,%7}, {%8,%9}, {%0,%1,%2,%3};\n"
        : "+f"(d[0]), "+f"(d[1]), "+f"(d[2]), "+f"(d[3])
        : "r"(a[0]), "r"(a[1]), "r"(a[2]), "r"(a[3]), "r"(b[0]), "r"(b[1]));
}

__device__ __forceinline__ void ldmx2t(uint32_t& b0, uint32_t& b1, uint32_t a) {
    asm volatile("ldmatrix.sync.aligned.m8n8.x2.trans.shared.b16 {%0,%1}, [%2];"
                 : "=r"(b0), "=r"(b1) : "r"(a));
}

__device__ __forceinline__ uint32_t smem_u32(const void* p) {
    uint32_t a;
    asm("{ .reg .u64 t; cvta.to.shared.u64 t, %1; cvt.u32.u64 %0, t; }"
        : "=r"(a) : "l"(p));
    return a;
}

__device__ __forceinline__ void cpa16(uint32_t dst, const void* src) {
    asm volatile("cp.async.cg.shared.global [%0], [%1], 16;"
                 :: "r"(dst), "l"(src) : "memory");
}
__device__ __forceinline__ void cpa16z(uint32_t dst, const void* src, int sz) {
    asm volatile("cp.async.cg.shared.global [%0], [%1], 16, %2;"
                 :: "r"(dst), "l"(src), "r"(sz) : "memory");
}
#define CPA_COMMIT() asm volatile("cp.async.commit_group;" ::: "memory")
#define CPA_WAIT0()  asm volatile("cp.async.wait_group 0;" ::: "memory")

__device__ __forceinline__ __nv_bfloat162 split_hi2(float x, float y) {
    return __nv_bfloat162(__float2bfloat16(x), __float2bfloat16(y));
}
__device__ __forceinline__ __nv_bfloat162 split_lo2(float x, float y) {
    float hx = __bfloat162float(__float2bfloat16(x));
    float hy = __bfloat162float(__float2bfloat16(y));
    return __nv_bfloat162(__float2bfloat16(x - hx), __float2bfloat16(y - hy));
}

// ====== one-shot W convert: pure elementwise, STG.64-packed ======

__global__ void __launch_bounds__(256) wconv_kernel(
    const float* __restrict__ Wq, const float* __restrict__ Wk,
    const float* __restrict__ Wv)
{
    const float* Wm[3] = {Wq, Wk, Wv};
    const float* Wg = Wm[blockIdx.x];
    __nv_bfloat16* whi = g_w_hi[blockIdx.x];
    __nv_bfloat16* wlo = g_w_lo[blockIdx.x];
    const int tid = threadIdx.x;
    const int k = blockIdx.y * 8 + (tid >> 5);
    const int n = (tid & 31) << 2;

    float4 w = *(const float4*)(Wg + (size_t)k * DD + n);
    int o = k * S136 + n;
    __nv_bfloat162 h01 = split_hi2(w.x, w.y), h23 = split_hi2(w.z, w.w);
    __nv_bfloat162 l01 = split_lo2(w.x, w.y), l23 = split_lo2(w.z, w.w);
    *(uint2*)(whi + o) = make_uint2(*(uint32_t*)&h01, *(uint32_t*)&h23);
    *(uint2*)(wlo + o) = make_uint2(*(uint32_t*)&l01, *(uint32_t*)&l23);
}

// ===================== QKV via mma.sync bf16 (R14 structure + cp.async) ====
// smem: x_hi@0 x_lo@17408 | W_hi@34816 W_lo@69632 (104448 total)

#define OFF_XHI 0
#define OFF_XLO 17408
#define OFF_WHI 34816
#define OFF_WLO 69632
#define W_U4    2176           /* uint4 count per hi (or lo) W array */
#define QKV_SMEM 104448

__global__ void __launch_bounds__(256) qkv_mma_kernel(
    const float* __restrict__ x,
    const float* __restrict__ bq, const float* __restrict__ bk,
    const float* __restrict__ bv)
{
    extern __shared__ char sb[];
    const uint32_t sbase = smem_u32(sb);
    const int tid  = threadIdx.x;
    const int wid  = tid >> 5;
    const int lane = tid & 31;
    const int row0 = blockIdx.x * 64;

    // ---- kick off W0 cp.async copy, then convert x tile (overlapped) ----
    {
        const uint4* shi = (const uint4*)g_w_hi[0];
        const uint4* slo = (const uint4*)g_w_lo[0];
        for (int i = tid; i < W_U4; i += 256) {
            cpa16(sbase + OFF_WHI + i * 16, shi + i);
            cpa16(sbase + OFF_WLO + i * 16, slo + i);
        }
        CPA_COMMIT();
    }
    for (int idx = tid; idx < 64 * 32; idx += 256) {
        int r = idx >> 5, k = (idx & 31) << 2;
        float4 v = *(const float4*)(x + (size_t)(row0 + r) * DD + k);
        int off = (r * S136 + k) * 2;
        *(__nv_bfloat162*)(sb + OFF_XHI + off)     = split_hi2(v.x, v.y);
        *(__nv_bfloat162*)(sb + OFF_XHI + off + 4) = split_hi2(v.z, v.w);
        *(__nv_bfloat162*)(sb + OFF_XLO + off)     = split_lo2(v.x, v.y);
        *(__nv_bfloat162*)(sb + OFF_XLO + off + 4) = split_lo2(v.z, v.w);
    }
    CPA_WAIT0();
    __syncthreads();

    const float* bias[3] = {bq, bk, bv};
    __nv_bfloat16* outh[3];
    __nv_bfloat16* outl[3];
    outh[0] = g_qh; outh[1] = g_kh; outh[2] = g_vh;
    outl[0] = g_ql; outl[1] = g_kl; outl[2] = g_vl;

    const int mw = wid & 1;
    const int nw = wid >> 1;
    const int ar = lane >> 2;
    const int ac = (lane & 3) << 2;

    for (int m = 0; m < 3; ++m) {
        if (m > 0) {
            __syncthreads();   // prior matrix's ldmatrix reads complete
            const uint4* shi = (const uint4*)g_w_hi[m];
            const uint4* slo = (const uint4*)g_w_lo[m];
            for (int i = tid; i < W_U4; i += 256) {
                cpa16(sbase + OFF_WHI + i * 16, shi + i);
                cpa16(sbase + OFF_WLO + i * 16, slo + i);
            }
            CPA_COMMIT();
            CPA_WAIT0();
            __syncthreads();
        }

        float acc[2][4][4];
        #pragma unroll
        for (int mt = 0; mt < 2; ++mt)
            #pragma unroll
            for (int nt = 0; nt < 4; ++nt)
                #pragma unroll
                for (int e = 0; e < 4; ++e) acc[mt][nt][e] = 0.f;

        #pragma unroll
        for (int ks = 0; ks < 8; ++ks) {
            const int kb = ks * 32;
            uint32_t ahi[2][4], alo[2][4];
            #pragma unroll
            for (int mt = 0; mt < 2; ++mt) {
                int abase = (mw * 32 + mt * 16 + ar) * 272 + kb + ac;
                ahi[mt][0] = *(const uint32_t*)(sb + OFF_XHI + abase);
                ahi[mt][1] = *(const uint32_t*)(sb + OFF_XHI + abase + 8*272);
                ahi[mt][2] = *(const uint32_t*)(sb + OFF_XHI + abase + 16);
                ahi[mt][3] = *(const uint32_t*)(sb + OFF_XHI + abase + 8*272 + 16);
                alo[mt][0] = *(const uint32_t*)(sb + OFF_XLO + abase);
                alo[mt][1] = *(const uint32_t*)(sb + OFF_XLO + abase + 8*272);
                alo[mt][2] = *(const uint32_t*)(sb + OFF_XLO + abase + 16);
                alo[mt][3] = *(const uint32_t*)(sb + OFF_XLO + abase + 8*272 + 16);
            }
            const uint32_t wrow = sbase + (ks * 16 + (lane & 15)) * 272;
            #pragma unroll
            for (int nt = 0; nt < 4; ++nt) {
                int n0 = nw * 32 + nt * 8;
                uint32_t bhi[2], blo[2];
                ldmx2t(bhi[0], bhi[1], wrow + OFF_WHI + n0 * 2);
                ldmx2t(blo[0], blo[1], wrow + OFF_WLO + n0 * 2);
                #pragma unroll
                for (int mt = 0; mt < 2; ++mt) {
                    mma16816(acc[mt][nt], ahi[mt], bhi);
                    mma16816(acc[mt][nt], ahi[mt], blo);
                    mma16816(acc[mt][nt], alo[mt], bhi);
                }
            }
        }

        // ---- epilogue: acc + bias -> split hi/lo bf16 globals ----
        const float* bp = bias[m];
        __nv_bfloat16* oh = outh[m];
        __nv_bfloat16* ol = outl[m];
        #pragma unroll
        for (int mt = 0; mt < 2; ++mt) {
            int grow = row0 + mw * 32 + mt * 16 + ar;
            #pragma unroll
            for (int nt = 0; nt < 4; ++nt) {
                int c = nw * 32 + nt * 8 + ((lane & 3) << 1);
                float2 b2 = *(const float2*)(bp + c);
                float v0x = acc[mt][nt][0] + b2.x;
                float v0y = acc[mt][nt][1] + b2.y;
                float v1x = acc[mt][nt][2] + b2.x;
                float v1y = acc[mt][nt][3] + b2.y;
                size_t o0 = (size_t)grow * DD + c;
                size_t o1 = (size_t)(grow + 8) * DD + c;
                *(__nv_bfloat162*)(oh + o0) = split_hi2(v0x, v0y);
                *(__nv_bfloat162*)(ol + o0) = split_lo2(v0x, v0y);
                *(__nv_bfloat162*)(oh + o1) = split_hi2(v1x, v1y);
                *(__nv_bfloat162*)(ol + o1) = split_lo2(v1x, v1y);
            }
        }
    }
}

// ===== attention: fragment-native softmax, single-phase PV, cp.async loads ==

#define AT_KHI 0
#define AT_KLO 43520
#define AT_QHI 87040
#define AT_QLO 95744
#define AT_VH   0
#define AT_VL   43520
#define AT_PTH  87040
#define AT_PTL  97792
#define AT_PMAX 108544
#define AT_PSUM 109056
#define AT_WS   109568
#define PTST 336
#define ATTN_SMEM 109696

__global__ void __launch_bounds__(256, 2) attn_kernel(float* __restrict__ outp)
{
    extern __shared__ char sb[];
    const uint32_t sbase = smem_u32(sb);
    const int tid  = threadIdx.x;
    const int wid  = tid >> 5;
    const int lane = tid & 31;
    const int blk  = blockIdx.x;
    const int b    = blk >> 7;
    const int s0   = (blk & 127) * TQ;
    const int lo   = s0 - HALF;

    const __nv_bfloat16* kh = g_kh + (size_t)b * SS * DD;
    const __nv_bfloat16* kl = g_kl + (size_t)b * SS * DD;
    const __nv_bfloat16* vh = g_vh + (size_t)b * SS * DD;
    const __nv_bfloat16* vl = g_vl + (size_t)b * SS * DD;
    const __nv_bfloat16* qh = g_qh + (size_t)b * SS * DD;
    const __nv_bfloat16* ql = g_ql + (size_t)b * SS * DD;

    // ---- cp.async k window (zero-fill OOB) + q tile ----
    for (int idx = tid; idx < KROWS * 16; idx += 256) {
        int r = idx >> 4, c = idx & 15;
        int g = lo + r;
        int gc = min(max(g, 0), SS - 1);
        int sz = ((unsigned)g < SS) ? 16 : 0;
        cpa16z(sbase + AT_KHI + r * 272 + (c << 4), kh + (size_t)gc * DD + (c << 3), sz);
        cpa16z(sbase + AT_KLO + r * 272 + (c << 4), kl + (size_t)gc * DD + (c << 3), sz);
    }
    for (int idx = tid; idx < TQ * 16; idx += 256) {
        int r = idx >> 4, c = idx & 15;
        cpa16(sbase + AT_QHI + r * 272 + (c << 4), qh + (size_t)(s0 + r) * DD + (c << 3));
        cpa16(sbase + AT_QLO + r * 272 + (c << 4), ql + (size_t)(s0 + r) * DD + (c << 3));
    }
    CPA_COMMIT();
    CPA_WAIT0();
    __syncthreads();

    const int mt = wid & 1;
    const int ng = wid >> 1;
    const int ar = lane >> 2;
    const int ac = (lane & 3) << 2;

    float sacc[5][4];
    #pragma unroll
    for (int nt = 0; nt < 5; ++nt)
        #pragma unroll
        for (int e = 0; e < 4; ++e) sacc[nt][e] = 0.f;

    #pragma unroll
    for (int ks = 0; ks < 8; ++ks) {
        const int kb = ks * 32;
        const int abase = (mt * 16 + ar) * 272 + kb + ac;
        uint32_t ahi[4], alo[4];
        ahi[0] = *(const uint32_t*)(sb + AT_QHI + abase);
        ahi[1] = *(const uint32_t*)(sb + AT_QHI + abase + 8*272);
        ahi[2] = *(const uint32_t*)(sb + AT_QHI + abase + 16);
        ahi[3] = *(const uint32_t*)(sb + AT_QHI + abase + 8*272 + 16);
        alo[0] = *(const uint32_t*)(sb + AT_QLO + abase);
        alo[1] = *(const uint32_t*)(sb + AT_QLO + abase + 8*272);
        alo[2] = *(const uint32_t*)(sb + AT_QLO + abase + 16);
        alo[3] = *(const uint32_t*)(sb + AT_QLO + abase + 8*272 + 16);
        #pragma unroll
        for (int nt = 0; nt < 5; ++nt) {
            int bbase = (ng * 40 + nt * 8 + ar) * 272 + kb + ac;
            uint32_t bhi[2], blo[2];
            bhi[0] = *(const uint32_t*)(sb + AT_KHI + bbase);
            bhi[1] = *(const uint32_t*)(sb + AT_KHI + bbase + 16);
            blo[0] = *(const uint32_t*)(sb + AT_KLO + bbase);
            blo[1] = *(const uint32_t*)(sb + AT_KLO + bbase + 16);
            mma16816(sacc[nt], ahi, bhi);
            mma16816(sacc[nt], ahi, blo);
            mma16816(sacc[nt], alo, bhi);
        }
    }

    const float scale = 0.08838834764831844f;
    const int r0 = mt * 16 + ar;
    const int r1 = r0 + 8;
    float gm0 = -INFINITY, gm1 = -INFINITY;
    #pragma unroll
    for (int nt = 0; nt < 5; ++nt) {
        int colb = ng * 40 + nt * 8 + ((lane & 3) << 1);
        #pragma unroll
        for (int u = 0; u < 2; ++u) {
            int col = colb + u;
            int g = lo + col;
            bool okg = ((unsigned)g < SS);
            int j0 = col - r0, j1 = col - r1;
            float v0 = (okg && j0 >= 0 && j0 <= 128) ? sacc[nt][u]   * scale : NEG_INF_F;
            float v1 = (okg && j1 >= 0 && j1 <= 128) ? sacc[nt][2+u] * scale : NEG_INF_F;
            sacc[nt][u]   = v0;
            sacc[nt][2+u] = v1;
            gm0 = fmaxf(gm0, v0);
            gm1 = fmaxf(gm1, v1);
        }
    }
    gm0 = fmaxf(gm0, __shfl_xor_sync(0xffffffffu, gm0, 1));
    gm0 = fmaxf(gm0, __shfl_xor_sync(0xffffffffu, gm0, 2));
    gm1 = fmaxf(gm1, __shfl_xor_sync(0xffffffffu, gm1, 1));
    gm1 = fmaxf(gm1, __shfl_xor_sync(0xffffffffu, gm1, 2));
    float ps0 = 0.f, ps1 = 0.f;
    #pragma unroll
    for (int nt = 0; nt < 5; ++nt) {
        #pragma unroll
        for (int u = 0; u < 2; ++u) {
            float e0 = __expf(sacc[nt][u]   - gm0);
            float e1 = __expf(sacc[nt][2+u] - gm1);
            sacc[nt][u]   = e0;
            sacc[nt][2+u] = e1;
            ps0 += e0;
            ps1 += e1;
        }
    }
    ps0 += __shfl_xor_sync(0xffffffffu, ps0, 1);
    ps0 += __shfl_xor_sync(0xffffffffu, ps0, 2);
    ps1 += __shfl_xor_sync(0xffffffffu, ps1, 1);
    ps1 += __shfl_xor_sync(0xffffffffu, ps1, 2);
    if ((lane & 3) == 0) {
        ((float*)(sb + AT_PMAX))[r0 * 4 + ng] = gm0;
        ((float*)(sb + AT_PMAX))[r1 * 4 + ng] = gm1;
        ((float*)(sb + AT_PSUM))[r0 * 4 + ng] = ps0;
        ((float*)(sb + AT_PSUM))[r1 * 4 + ng] = ps1;
    }
    __syncthreads();   // partials visible; k & q dead

    // ---- cp.async full v tile (overlaps the combine below) ----
    for (int idx = tid; idx < KROWS * 16; idx += 256) {
        int r = idx >> 4, c = idx & 15;
        int gc = min(max(lo + r, 0), SS - 1);
        cpa16(sbase + AT_VH + r * 272 + (c << 4), vh + (size_t)gc * DD + (c << 3));
        cpa16(sbase + AT_VL + r * 272 + (c << 4), vl + (size_t)gc * DD + (c << 3));
    }
    CPA_COMMIT();

    {
        float4 m40 = *(const float4*)((const float*)(sb + AT_PMAX) + r0 * 4);
        float4 m41 = *(const float4*)((const float*)(sb + AT_PMAX) + r1 * 4);
        float4 s40 = *(const float4*)((const float*)(sb + AT_PSUM) + r0 * 4);
        float4 s41 = *(const float4*)((const float*)(sb + AT_PSUM) + r1 * 4);
        float m0 = fmaxf(fmaxf(m40.x, m40.y), fmaxf(m40.z, m40.w));
        float m1 = fmaxf(fmaxf(m41.x, m41.y), fmaxf(m41.z, m41.w));
        float s0w = s40.x * __expf(m40.x - m0) + s40.y * __expf(m40.y - m0)
                  + s40.z * __expf(m40.z - m0) + s40.w * __expf(m40.w - m0);
        float s1w = s41.x * __expf(m41.x - m1) + s41.y * __expf(m41.y - m1)
                  + s41.z * __expf(m41.z - m1) + s41.w * __expf(m41.w - m1);
        if ((lane & 3) == 0 && ng == 0) {
            ((float*)(sb + AT_WS))[r0] = s0w;
            ((float*)(sb + AT_WS))[r1] = s1w;
        }
        float f0 = __expf(gm0 - m0);
        float f1 = __expf(gm1 - m1);
        #pragma unroll
        for (int nt = 0; nt < 5; ++nt) {
            int cb = (ng * 40 + nt * 8 + ((lane & 3) << 1)) * 2;
            float p00 = sacc[nt][0] * f0, p01 = sacc[nt][1] * f0;
            float p10 = sacc[nt][2] * f1, p11 = sacc[nt][3] * f1;
            *(__nv_bfloat162*)(sb + AT_PTH + r0 * PTST + cb) = split_hi2(p00, p01);
            *(__nv_bfloat162*)(sb + AT_PTL + r0 * PTST + cb) = split_lo2(p00, p01);
            *(__nv_bfloat162*)(sb + AT_PTH + r1 * PTST + cb) = split_hi2(p10, p11);
            *(__nv_bfloat162*)(sb + AT_PTL + r1 * PTST + cb) = split_lo2(p10, p11);
        }
    }
    CPA_WAIT0();
    __syncthreads();

    float oacc[4][4];
    #pragma unroll
    for (int nt = 0; nt < 4; ++nt)
        #pragma unroll
        for (int e = 0; e < 4; ++e) oacc[nt][e] = 0.f;

    #pragma unroll
    for (int ks = 0; ks < 10; ++ks) {
        const int abase = (mt * 16 + ar) * PTST + ks * 32 + ac;
        uint32_t phi[4], plo[4];
        phi[0] = *(const uint32_t*)(sb + AT_PTH + abase);
        phi[1] = *(const uint32_t*)(sb + AT_PTH + abase + 8*PTST);
        phi[2] = *(const uint32_t*)(sb + AT_PTH + abase + 16);
        phi[3] = *(const uint32_t*)(sb + AT_PTH + abase + 8*PTST + 16);
        plo[0] = *(const uint32_t*)(sb + AT_PTL + abase);
        plo[1] = *(const uint32_t*)(sb + AT_PTL + abase + 8*PTST);
        plo[2] = *(const uint32_t*)(sb + AT_PTL + abase + 16);
        plo[3] = *(const uint32_t*)(sb + AT_PTL + abase + 8*PTST + 16);
        const uint32_t vrow = sbase + AT_VH + (ks * 16 + (lane & 15)) * 272;
        #pragma unroll
        for (int nt = 0; nt < 4; ++nt) {
            int n0 = ng * 32 + nt * 8;
            uint32_t vhf[2], vlf[2];
            ldmx2t(vhf[0], vhf[1], vrow + n0 * 2);
            ldmx2t(vlf[0], vlf[1], vrow + (AT_VL - AT_VH) + n0 * 2);
            mma16816(oacc[nt], phi, vhf);
            mma16816(oacc[nt], phi, vlf);
            mma16816(oacc[nt], plo, vhf);
        }
    }

    {
        const float* ws = (const float*)(sb + AT_WS);
        float inv0 = 1.0f / ws[r0];
        float inv1 = 1.0f / ws[r1];
        float* op0 = outp + ((size_t)b * SS + s0 + r0) * DD;
        float* op1 = outp + ((size_t)b * SS + s0 + r1) * DD;
        #pragma unroll
        for (int nt = 0; nt < 4; ++nt) {
            int c = ng * 32 + nt * 8 + ((lane & 3) << 1);
            *(float2*)(op0 + c) = make_float2(oacc[nt][0] * inv0, oacc[nt][1] * inv0);
            *(float2*)(op1 + c) = make_float2(oacc[nt][2] * inv1, oacc[nt][3] * inv1);
        }
    }
}

extern "C" void kernel_launch(void* const* d_in, const int* in_sizes, int n_in,
                              void* d_out, int out_size)
{
    const float* x  = (const float*)d_in[0];
    const float* Wq = (const float*)d_in[1];
    const float* bq = (const float*)d_in[2];
    const float* Wk = (const float*)d_in[3];
    const float* bk = (const float*)d_in[4];
    const float* Wv = (const float*)d_in[5];
    const float* bv = (const float*)d_in[6];
    float* out = (float*)d_out;

    cudaFuncSetAttribute(qkv_mma_kernel,
                         cudaFuncAttributeMaxDynamicSharedMemorySize, QKV_SMEM);
    cudaFuncSetAttribute(attn_kernel,
                         cudaFuncAttributeMaxDynamicSharedMemorySize, ATTN_SMEM);

    wconv_kernel<<<dim3(3, 16), 256>>>(Wq, Wk, Wv);
    qkv_mma_kernel<<<BB * SS / 64, 256, QKV_SMEM>>>(x, bq, bk, bv);
    attn_kernel<<<BB * SS / TQ, 256, ATTN_SMEM>>>(out);
}